// round 5
// baseline (speedup 1.0000x reference)
#include <cuda_runtime.h>
#include <math.h>

#define Bn 16
#define Tn 12
#define Nn 325
#define Fn 64
#define KHn 4
#define Dn 16
#define KDn 3
#define BTn (Bn*Tn)            // 192
#define BTNn (BTn*Nn)          // 62400
#define NNn (Nn*Nn)            // 105625

typedef unsigned long long ull;

// ---------------- f32x2 packed helpers (FFMA2 — PTX-only on sm_103a) ----------------
__device__ __forceinline__ ull pack2(float lo, float hi) {
    ull r; asm("mov.b64 %0, {%1, %2};" : "=l"(r) : "f"(lo), "f"(hi)); return r;
}
__device__ __forceinline__ float2 unpack2(ull v) {
    float lo, hi; asm("mov.b64 {%0, %1}, %2;" : "=f"(lo), "=f"(hi) : "l"(v));
    return make_float2(lo, hi);
}
__device__ __forceinline__ ull ffma2(ull a, ull b, ull c) {
    ull d; asm("fma.rn.f32x2 %0, %1, %2, %3;" : "=l"(d) : "l"(a), "l"(b), "l"(c)); return d;
}
__device__ __forceinline__ ull fmul2(ull a, ull b) {
    ull d; asm("mul.rn.f32x2 %0, %1, %2;" : "=l"(d) : "l"(a), "l"(b)); return d;
}

// ---------------- scratch (device globals; no allocation allowed) ----------------
__device__ float g_q [KHn*BTNn*Dn + 16];
__device__ float g_k [KHn*BTNn*Dn + 16];
__device__ float g_ks[KHn*BTNn*Dn + 16];
__device__ float g_v [KHn*BTNn*Dn + 16];
__device__ float g_vs[KHn*BTNn*Dn + 16];
__device__ float g_biasT[KHn*NNn + 384];   // transposed [h][m][n]
__device__ float g_val[BTNn*Fn];

// ---------------- kernel 1: graph-diffusion bias, transposed output ----------------
__global__ void bias_kernel(const float* __restrict__ A, const float* __restrict__ AT,
                            const float* __restrict__ Wdi, const float* __restrict__ Wdo)
{
    __shared__ float tile[32][33];
    int h = blockIdx.z;
    int n0 = blockIdx.x*32, m0 = blockIdx.y*32;
    int tx = threadIdx.x, ty = threadIdx.y;    // 32 x 8

#pragma unroll
    for (int k = 0; k < 4; ++k) {
        int n = n0 + ty + 8*k, m = m0 + tx;
        float s = 0.f;
        if (n < Nn && m < Nn) {
            int nm = n*Nn + m;
            if (h < 2) {
#pragma unroll
                for (int j = 0; j < KDn; ++j) s = fmaf(Wdi[(h*KDn+j)*NNn+nm], A[j*NNn+nm], s);
            } else {
#pragma unroll
                for (int j = 0; j < KDn; ++j) s = fmaf(Wdo[((h-2)*KDn+j)*NNn+nm], AT[j*NNn+nm], s);
            }
        }
        tile[ty + 8*k][tx] = s;
    }
    __syncthreads();
#pragma unroll
    for (int k = 0; k < 4; ++k) {
        int m = m0 + ty + 8*k, n = n0 + tx;
        if (m < Nn && n < Nn)
            g_biasT[(size_t)h*NNn + (size_t)m*Nn + n] = tile[tx][ty + 8*k];
    }
}

// ---------------- kernel 2: projection (grid.y selects which of the 5) ----------------
__global__ __launch_bounds__(256) void proj_kernel(
    const float* __restrict__ x,
    const float* __restrict__ Wq,  const float* __restrict__ bq,
    const float* __restrict__ Wk,  const float* __restrict__ bk,
    const float* __restrict__ Wks, const float* __restrict__ bks,
    const float* __restrict__ Wv,  const float* __restrict__ bv,
    const float* __restrict__ Wvs, const float* __restrict__ bvs)
{
    extern __shared__ float sm[];
    float* sW   = sm;                 // 64*68 = 4352
    float* sb   = sm + 4352;          // 64
    float* srow = sm + 4416;          // 8 warps * 512 = 4096

    int p = blockIdx.y;
    const float* W = (p==0)?Wq:(p==1)?Wk:(p==2)?Wks:(p==3)?Wv:Wvs;
    const float* bb = (p==0)?bq:(p==1)?bk:(p==2)?bks:(p==3)?bv:bvs;
    float* o = (p==0)?g_q:(p==1)?g_k:(p==2)?g_ks:(p==3)?g_v:g_vs;

    for (int i = threadIdx.x; i < 4096; i += 256) {
        int f = i >> 6, c = i & 63;
        sW[f*68 + c] = W[i];
    }
    if (threadIdx.x < 64) sb[threadIdx.x] = bb[threadIdx.x];

    int warp = threadIdx.x >> 5, lane = threadIdx.x & 31;
    int r0 = blockIdx.x * 64 + warp * 8;
    float* myrow = srow + warp*512;
    {
        const float* xs = x + (size_t)r0*64;
        for (int i = lane; i < 512; i += 32) myrow[i] = xs[i];
    }
    __syncthreads();

    int f0 = lane, f1 = lane + 32;
    int h0 = f0 >> 4, d0 = f0 & 15;
    int h1 = f1 >> 4, d1 = f1 & 15;

    ull acc0[8], acc1[8];
    ull zero = pack2(0.f, 0.f);
#pragma unroll
    for (int r = 0; r < 8; ++r) { acc0[r] = zero; acc1[r] = zero; }
#pragma unroll 4
    for (int c = 0; c < 64; c += 4) {
        ulonglong2 w0 = *(const ulonglong2*)(sW + f0*68 + c);
        ulonglong2 w1 = *(const ulonglong2*)(sW + f1*68 + c);
#pragma unroll
        for (int r = 0; r < 8; ++r) {
            ulonglong2 xv = *(const ulonglong2*)(myrow + r*64 + c);
            acc0[r] = ffma2(xv.x, w0.x, acc0[r]);
            acc1[r] = ffma2(xv.x, w1.x, acc1[r]);
            acc0[r] = ffma2(xv.y, w0.y, acc0[r]);
            acc1[r] = ffma2(xv.y, w1.y, acc1[r]);
        }
    }
    float bb0 = sb[f0], bb1 = sb[f1];
#pragma unroll
    for (int r = 0; r < 8; ++r) {
        size_t rr = (size_t)(r0 + r);
        float2 a0 = unpack2(acc0[r]);
        float2 a1 = unpack2(acc1[r]);
        o[((size_t)h0*BTNn + rr)*Dn + d0] = a0.x + a0.y + bb0;
        o[((size_t)h1*BTNn + rr)*Dn + d1] = a1.x + a1.y + bb1;
    }
}

// ---------------- kernel 3: attention ----------------
// grid (BT, KH); block 192 threads. Each thread handles 2 query rows (n, n+163),
// sharing the per-key K/V smem loads. All inner math in f32x2.
#define ATH 192
#define QSPLIT 163
__global__ __launch_bounds__(ATH) void attn_kernel()
{
    extern __shared__ float sm[];
    float* sk = sm;              // 325*16 = 5200
    float* sv = sm + 5200;       // 5200

    int bt = blockIdx.x, h = blockIdx.y;
    size_t base = ((size_t)h*BTNn + (size_t)bt*Nn)*Dn;

    {
        const float4* kb = (const float4*)(g_k + base);
        const float4* vb = (const float4*)(g_v + base);
        float4* k4 = (float4*)sk;
        float4* v4 = (float4*)sv;
        for (int i = threadIdx.x; i < Nn*Dn/4; i += ATH) {
            k4[i] = kb[i];
            v4[i] = vb[i];
        }
    }
    __syncthreads();

    int t = threadIdx.x;
    if (t >= QSPLIT) return;
    int n0 = t;
    bool has1 = (t + QSPLIT < Nn);
    int n1 = has1 ? (t + QSPLIT) : n0;

    ull q0p[8], q1p[8], o0p[8], o1p[8];
    float l0 = 0.f, l1 = 0.f, es0, es1;
    {
        const ulonglong2* qp0 = (const ulonglong2*)(g_q  + base + (size_t)n0*Dn);
        const ulonglong2* qp1 = (const ulonglong2*)(g_q  + base + (size_t)n1*Dn);
        const ulonglong2* kp0 = (const ulonglong2*)(g_ks + base + (size_t)n0*Dn);
        const ulonglong2* kp1 = (const ulonglong2*)(g_ks + base + (size_t)n1*Dn);
        ull s0 = pack2(0.f,0.f), s1 = s0;
#pragma unroll
        for (int i = 0; i < 4; ++i) {
            ulonglong2 a0 = qp0[i], b0 = kp0[i];
            ulonglong2 a1 = qp1[i], b1 = kp1[i];
            q0p[2*i] = a0.x;  q0p[2*i+1] = a0.y;
            q1p[2*i] = a1.x;  q1p[2*i+1] = a1.y;
            s0 = ffma2(a0.x, b0.x, s0);  s0 = ffma2(a0.y, b0.y, s0);
            s1 = ffma2(a1.x, b1.x, s1);  s1 = ffma2(a1.y, b1.y, s1);
        }
        float2 f0 = unpack2(s0), f1 = unpack2(s1);
        es0 = 1.f/(1.f + __expf(-(f0.x+f0.y)*0.25f));
        es1 = 1.f/(1.f + __expf(-(f1.x+f1.y)*0.25f));
        ull zero = pack2(0.f,0.f);
#pragma unroll
        for (int i = 0; i < 8; ++i) { o0p[i] = zero; o1p[i] = zero; }
    }

    const float* bT = g_biasT + (size_t)h*NNn;

#pragma unroll 2
    for (int m = 0; m < Nn; ++m) {
        float b0 = __ldg(bT + (size_t)m*Nn + n0);
        float b1 = __ldg(bT + (size_t)m*Nn + n1);
        const ulonglong2* kr = (const ulonglong2*)(sk + m*16);
        ulonglong2 ka = kr[0], kb2 = kr[1], kc = kr[2], kd = kr[3];
        ull s0 = fmul2(q0p[0], ka.x);
        ull s1 = fmul2(q1p[0], ka.x);
        s0 = ffma2(q0p[1], ka.y,  s0);  s1 = ffma2(q1p[1], ka.y,  s1);
        s0 = ffma2(q0p[2], kb2.x, s0);  s1 = ffma2(q1p[2], kb2.x, s1);
        s0 = ffma2(q0p[3], kb2.y, s0);  s1 = ffma2(q1p[3], kb2.y, s1);
        s0 = ffma2(q0p[4], kc.x,  s0);  s1 = ffma2(q1p[4], kc.x,  s1);
        s0 = ffma2(q0p[5], kc.y,  s0);  s1 = ffma2(q1p[5], kc.y,  s1);
        s0 = ffma2(q0p[6], kd.x,  s0);  s1 = ffma2(q1p[6], kd.x,  s1);
        s0 = ffma2(q0p[7], kd.y,  s0);  s1 = ffma2(q1p[7], kd.y,  s1);
        float2 f0 = unpack2(s0), f1 = unpack2(s1);
        float p0 = __expf(fmaf(f0.x + f0.y, 0.25f, b0));
        float p1 = __expf(fmaf(f1.x + f1.y, 0.25f, b1));
        l0 += p0; l1 += p1;
        ull pp0 = pack2(p0, p0), pp1 = pack2(p1, p1);
        const ulonglong2* vr = (const ulonglong2*)(sv + m*16);
        ulonglong2 va = vr[0], vb2 = vr[1], vc = vr[2], vd = vr[3];
        o0p[0] = ffma2(pp0, va.x,  o0p[0]);  o1p[0] = ffma2(pp1, va.x,  o1p[0]);
        o0p[1] = ffma2(pp0, va.y,  o0p[1]);  o1p[1] = ffma2(pp1, va.y,  o1p[1]);
        o0p[2] = ffma2(pp0, vb2.x, o0p[2]);  o1p[2] = ffma2(pp1, vb2.x, o1p[2]);
        o0p[3] = ffma2(pp0, vb2.y, o0p[3]);  o1p[3] = ffma2(pp1, vb2.y, o1p[3]);
        o0p[4] = ffma2(pp0, vc.x,  o0p[4]);  o1p[4] = ffma2(pp1, vc.x,  o1p[4]);
        o0p[5] = ffma2(pp0, vc.y,  o0p[5]);  o1p[5] = ffma2(pp1, vc.y,  o1p[5]);
        o0p[6] = ffma2(pp0, vd.x,  o0p[6]);  o1p[6] = ffma2(pp1, vd.x,  o1p[6]);
        o0p[7] = ffma2(pp0, vd.y,  o0p[7]);  o1p[7] = ffma2(pp1, vd.y,  o1p[7]);
    }

    {
        float inv0 = 1.f/(es0 + l0);
        const float* vsp = g_vs + base + (size_t)n0*Dn;
        float* outp = g_val + ((size_t)bt*Nn + n0)*Fn + h*Dn;
#pragma unroll
        for (int i = 0; i < 4; ++i) {
            float2 oa = unpack2(o0p[2*i]), ob = unpack2(o0p[2*i+1]);
            float4 vs = *(const float4*)(vsp + 4*i);
            float4 r;
            r.x = fmaf(oa.x - l0*vs.x, inv0, vs.x);
            r.y = fmaf(oa.y - l0*vs.y, inv0, vs.y);
            r.z = fmaf(ob.x - l0*vs.z, inv0, vs.z);
            r.w = fmaf(ob.y - l0*vs.w, inv0, vs.w);
            *(float4*)(outp + 4*i) = r;
        }
    }
    if (has1) {
        float inv1 = 1.f/(es1 + l1);
        const float* vsp = g_vs + base + (size_t)n1*Dn;
        float* outp = g_val + ((size_t)bt*Nn + n1)*Fn + h*Dn;
#pragma unroll
        for (int i = 0; i < 4; ++i) {
            float2 oa = unpack2(o1p[2*i]), ob = unpack2(o1p[2*i+1]);
            float4 vs = *(const float4*)(vsp + 4*i);
            float4 r;
            r.x = fmaf(oa.x - l1*vs.x, inv1, vs.x);
            r.y = fmaf(oa.y - l1*vs.y, inv1, vs.y);
            r.z = fmaf(ob.x - l1*vs.z, inv1, vs.z);
            r.w = fmaf(ob.y - l1*vs.w, inv1, vs.w);
            *(float4*)(outp + 4*i) = r;
        }
    }
}

// ---------------- kernel 4: FFN(gelu) + residual + LayerNorm ----------------
__global__ __launch_bounds__(256) void ffn_kernel(
    const float* __restrict__ x,
    const float* __restrict__ Wf1, const float* __restrict__ bf1,
    const float* __restrict__ Wf2, const float* __restrict__ bf2,
    const float* __restrict__ gln, const float* __restrict__ bln,
    float* __restrict__ out)
{
    extern __shared__ float sm[];
    float* sW1 = sm;            // 4352
    float* sW2 = sm + 4352;     // 4352
    float* sb1 = sm + 8704;     // 64
    float* sb2 = sm + 8768;     // 64
    float* sg  = sm + 8832;     // 64
    float* sbl = sm + 8896;     // 64
    float* srow = sm + 8960;    // 8 * 512 = 4096

    for (int i = threadIdx.x; i < 4096; i += 256) {
        int f = i >> 6, c = i & 63;
        sW1[f*68+c] = Wf1[i];
        sW2[f*68+c] = Wf2[i];
    }
    if (threadIdx.x < 64) {
        sb1[threadIdx.x] = bf1[threadIdx.x];
        sb2[threadIdx.x] = bf2[threadIdx.x];
        sg [threadIdx.x] = gln[threadIdx.x];
        sbl[threadIdx.x] = bln[threadIdx.x];
    }

    int warp = threadIdx.x >> 5, lane = threadIdx.x & 31;
    int r0 = blockIdx.x*64 + warp*8;
    float* myrow = srow + warp*512;
    {
        const float* vs = g_val + (size_t)r0*64;
        for (int i = lane; i < 512; i += 32) myrow[i] = vs[i];
    }
    __syncthreads();

    int f0 = lane, f1 = lane + 32;
    ull zero = pack2(0.f, 0.f);
    ull a0[8], a1[8];
#pragma unroll
    for (int r = 0; r < 8; ++r) { a0[r] = zero; a1[r] = zero; }
#pragma unroll 4
    for (int c = 0; c < 64; c += 4) {
        ulonglong2 w0 = *(const ulonglong2*)(sW1 + f0*68 + c);
        ulonglong2 w1 = *(const ulonglong2*)(sW1 + f1*68 + c);
#pragma unroll
        for (int r = 0; r < 8; ++r) {
            ulonglong2 xv = *(const ulonglong2*)(myrow + r*64 + c);
            a0[r] = ffma2(xv.x, w0.x, a0[r]);
            a1[r] = ffma2(xv.x, w1.x, a1[r]);
            a0[r] = ffma2(xv.y, w0.y, a0[r]);
            a1[r] = ffma2(xv.y, w1.y, a1[r]);
        }
    }
    float t0[8], t1[8];
#pragma unroll
    for (int r = 0; r < 8; ++r) {
        float2 u0 = unpack2(a0[r]), u1 = unpack2(a1[r]);
        t0[r] = u0.x + u0.y + sb1[f0];
        t1[r] = u1.x + u1.y + sb1[f1];
        t0[r] = 0.5f*t0[r]*(1.f + erff(t0[r]*0.7071067811865476f));
        t1[r] = 0.5f*t1[r]*(1.f + erff(t1[r]*0.7071067811865476f));
    }
    __syncwarp();
#pragma unroll
    for (int r = 0; r < 8; ++r) { myrow[r*64+f0] = t0[r]; myrow[r*64+f1] = t1[r]; }
    __syncwarp();

    ull b0[8], b1[8];
#pragma unroll
    for (int r = 0; r < 8; ++r) { b0[r] = zero; b1[r] = zero; }
#pragma unroll 4
    for (int c = 0; c < 64; c += 4) {
        ulonglong2 w0 = *(const ulonglong2*)(sW2 + f0*68 + c);
        ulonglong2 w1 = *(const ulonglong2*)(sW2 + f1*68 + c);
#pragma unroll
        for (int r = 0; r < 8; ++r) {
            ulonglong2 xv = *(const ulonglong2*)(myrow + r*64 + c);
            b0[r] = ffma2(xv.x, w0.x, b0[r]);
            b1[r] = ffma2(xv.x, w1.x, b1[r]);
            b0[r] = ffma2(xv.y, w0.y, b0[r]);
            b1[r] = ffma2(xv.y, w1.y, b1[r]);
        }
    }
    const float* xr = x + (size_t)r0*64;
#pragma unroll
    for (int r = 0; r < 8; ++r) {
        float2 u0 = unpack2(b0[r]), u1 = unpack2(b1[r]);
        float h0 = u0.x + u0.y + sb2[f0] + xr[r*64+f0];
        float h1 = u1.x + u1.y + sb2[f1] + xr[r*64+f1];
        float s1 = h0 + h1;
        float s2 = fmaf(h0, h0, h1*h1);
#pragma unroll
        for (int oo = 16; oo; oo >>= 1) {
            s1 += __shfl_xor_sync(0xffffffffu, s1, oo);
            s2 += __shfl_xor_sync(0xffffffffu, s2, oo);
        }
        float mean = s1 * (1.f/64.f);
        float var  = s2 * (1.f/64.f) - mean*mean;
        float rs   = rsqrtf(var + 1e-5f);
        out[(size_t)(r0+r)*64 + f0] = fmaf(sg[f0], (h0-mean)*rs, sbl[f0]);
        out[(size_t)(r0+r)*64 + f1] = fmaf(sg[f1], (h1-mean)*rs, sbl[f1]);
    }
}

// ---------------- launch ----------------
extern "C" void kernel_launch(void* const* d_in, const int* in_sizes, int n_in,
                              void* d_out, int out_size)
{
    const float* x   = (const float*)d_in[0];
    const float* A   = (const float*)d_in[1];
    const float* AT  = (const float*)d_in[2];
    const float* Wq  = (const float*)d_in[3];
    const float* bq  = (const float*)d_in[4];
    const float* Wk  = (const float*)d_in[5];
    const float* bk  = (const float*)d_in[6];
    const float* Wks = (const float*)d_in[7];
    const float* bks = (const float*)d_in[8];
    const float* Wv  = (const float*)d_in[9];
    const float* bv  = (const float*)d_in[10];
    const float* Wvs = (const float*)d_in[11];
    const float* bvs = (const float*)d_in[12];
    const float* Wdi = (const float*)d_in[13];
    const float* Wdo = (const float*)d_in[14];
    const float* Wf1 = (const float*)d_in[15];
    const float* bf1 = (const float*)d_in[16];
    const float* Wf2 = (const float*)d_in[17];
    const float* bf2 = (const float*)d_in[18];
    const float* gln = (const float*)d_in[19];
    const float* bln = (const float*)d_in[20];
    float* out = (float*)d_out;

    cudaFuncSetAttribute(proj_kernel, cudaFuncAttributeMaxDynamicSharedMemorySize, 34048);
    cudaFuncSetAttribute(attn_kernel, cudaFuncAttributeMaxDynamicSharedMemorySize, 41600);
    cudaFuncSetAttribute(ffn_kernel,  cudaFuncAttributeMaxDynamicSharedMemorySize, 52224);

    dim3 bg(11, 11, 4);
    bias_kernel<<<bg, dim3(32, 8)>>>(A, AT, Wdi, Wdo);
    dim3 pg(975, 5);
    proj_kernel<<<pg, 256, 34048>>>(x, Wq, bq, Wk, bk, Wks, bks, Wv, bv, Wvs, bvs);
    dim3 ag(BTn, KHn);
    attn_kernel<<<ag, ATH, 41600>>>();
    ffn_kernel<<<975, 256, 52224>>>(x, Wf1, bf1, Wf2, bf2, gln, bln, out);
}